// round 3
// baseline (speedup 1.0000x reference)
#include <cuda_runtime.h>

#define NN 50000
#define NE 200000
#define ND 32
#define ED 16
#define HD 32
#define OD 32
#define NCOL 1024            // HD*OD
#define EPSV 1e-5f
#define SLOPE 0.01f

#define NWARP 8
#define BLOCK 256
#define EGRID 148

// folded weights (BN absorbed)
__device__ float g_W2f[HD * NCOL];   // [k][c] row-major, c = i*32+o
__device__ float g_b2f[NCOL];
__device__ float g_W1f[ED * HD];     // [d][c]
__device__ float g_b1f[HD];
__device__ int   g_is64;

// ---------------------------------------------------------------------------
// Fold BN into linear weights (one thread per W2 element); detect edge_index
// dtype (int32 vs int64).
// ---------------------------------------------------------------------------
__global__ void fold_kernel(const float* __restrict__ W1, const float* __restrict__ b1,
                            const float* __restrict__ g1, const float* __restrict__ be1,
                            const float* __restrict__ m1, const float* __restrict__ v1,
                            const float* __restrict__ W2, const float* __restrict__ b2,
                            const float* __restrict__ g2, const float* __restrict__ be2,
                            const float* __restrict__ m2, const float* __restrict__ v2,
                            const int* __restrict__ ei32)
{
    int idx = blockIdx.x * blockDim.x + threadIdx.x;   // 0 .. HD*NCOL-1
    if (idx >= HD * NCOL) return;
    int c = idx & (NCOL - 1);
    int k = idx >> 10;
    float s = g2[c] * rsqrtf(v2[c] + EPSV);
    g_W2f[idx] = W2[idx] * s;
    if (k == 0) {
        g_b2f[c] = (b2[c] - m2[c]) * s + be2[c];
        if (c < HD) {
            float s1 = g1[c] * rsqrtf(v1[c] + EPSV);
            g_b1f[c] = (b1[c] - m1[c]) * s1 + be1[c];
            #pragma unroll
            for (int d = 0; d < ED; d++)
                g_W1f[d * HD + c] = W1[d * HD + c] * s1;
        }
        if (c == 0) {
            // int64 little-endian: high words (odd int32 slots) are all zero
            // (node ids nonneg < 2^31). 64 samples -> false-pos prob ~0.
            int all0 = 1;
            for (int i = 0; i < 64; i++)
                if (ei32[2 * i + 1] != 0) { all0 = 0; break; }
            g_is64 = all0;
        }
    }
}

// ---------------------------------------------------------------------------
// out[n,:] = bias + x[n,:] @ root    (one warp per node)
// ---------------------------------------------------------------------------
__global__ void init_kernel(const float* __restrict__ x,
                            const float* __restrict__ root,
                            const float* __restrict__ bias,
                            float* __restrict__ out)
{
    __shared__ float root_s[ND * OD];
    __shared__ float bias_s[OD];
    int t = threadIdx.x;
    for (int i = t; i < ND * OD; i += blockDim.x) root_s[i] = root[i];
    if (t < OD) bias_s[t] = bias[t];
    __syncthreads();

    int lane = t & 31, w = t >> 5;
    int n = blockIdx.x * (blockDim.x >> 5) + w;
    if (n >= NN) return;

    float xv = x[n * ND + lane];
    float acc = bias_s[lane];
    #pragma unroll
    for (int i = 0; i < ND; i++)
        acc = fmaf(__shfl_sync(0xffffffffu, xv, i), root_s[i * OD + lane], acc);
    out[n * OD + lane] = acc;
}

// ---------------------------------------------------------------------------
// Fused edge kernel, packed f32x2 (FFMA2) version.
// 4 edges per warp; accumulators t01/t23 hold edge pairs as f32x2.
// Per (k,i): 1 LDS.32 (wv) + 1 mov.b64 pack + 2 fma.rn.f32x2  -> 2x the FMA
// lanes per fma-pipe issue slot vs scalar FFMA.
// ---------------------------------------------------------------------------
extern __shared__ float smem[];

__global__ void __launch_bounds__(BLOCK, 1)
edge_kernel(const float* __restrict__ x,
            const int*   __restrict__ ei32,
            const float* __restrict__ edge_attr,
            float* __restrict__ out)
{
    float* W2s = smem;                 // 32768 floats
    float* b2s = W2s + HD * NCOL;      // 1024
    float* W1s = b2s + NCOL;           // 512
    float* b1s = W1s + ED * HD;        // 32
    float* stg = b1s + HD;             // 8 warps * 320 floats

    int tid = threadIdx.x;
    // cooperative smem fill (vectorized)
    {
        const float4* src = (const float4*)g_W2f;
        float4* dst4 = (float4*)W2s;
        for (int i = tid; i < (HD * NCOL) / 4; i += BLOCK) dst4[i] = src[i];
        for (int i = tid; i < NCOL; i += BLOCK) b2s[i] = g_b2f[i];
        for (int i = tid; i < ED * HD; i += BLOCK) W1s[i] = g_W1f[i];
        if (tid < HD) b1s[tid] = g_b1f[tid];
    }
    __syncthreads();

    int lane = tid & 31, wid = tid >> 5;
    float* ea  = stg + wid * 320;      // [4][16]
    float* xjT = ea + 64;              // [i][e] : 32*4, 16B-aligned
    float* hhT = xjT + 128;            // [k][e] : 32*4,  8B-aligned

    int is64 = g_is64;
    const int ngroups = NE / 4;        // 50000, exact

    for (int g = blockIdx.x * NWARP + wid; g < ngroups; g += (int)gridDim.x * NWARP) {
        int e0 = g * 4;
        int dsts[4];
        #pragma unroll
        for (int e = 0; e < 4; e++) {
            int eid = e0 + e;
            int s = is64 ? ei32[2 * eid]        : ei32[eid];
            int d = is64 ? ei32[2 * (NE + eid)] : ei32[NE + eid];
            dsts[e] = d;
            xjT[lane * 4 + e] = x[s * ND + lane];     // transposed store
            if (lane < ED) ea[e * ED + lane] = edge_attr[eid * ED + lane];
        }
        __syncwarp();

        // first layer (folded BN) + leaky, stored transposed hhT[k][e]
        #pragma unroll
        for (int e = 0; e < 4; e++) {
            float a = b1s[lane];
            #pragma unroll
            for (int d = 0; d < ED; d++)
                a = fmaf(ea[e * ED + d], W1s[d * HD + lane], a);
            hhT[lane * 4 + e] = fmaxf(a, SLOPE * a);
        }
        __syncwarp();

        // second layer: packed accumulators, lane = o
        unsigned long long t01[32], t23[32];
        #pragma unroll
        for (int i = 0; i < 32; i++) {
            float b = b2s[i * 32 + lane];
            unsigned long long bb;
            asm("mov.b64 %0, {%1, %1};" : "=l"(bb) : "f"(b));
            t01[i] = bb; t23[i] = bb;
        }

        #pragma unroll 2
        for (int k = 0; k < HD; k++) {
            unsigned long long h01 = *(const unsigned long long*)(hhT + k * 4);
            unsigned long long h23 = *(const unsigned long long*)(hhT + k * 4 + 2);
            const float* wr = W2s + k * NCOL + lane;
            #pragma unroll
            for (int i = 0; i < 32; i++) {
                float wv = wr[i * 32];
                unsigned long long wvv;
                asm("mov.b64 %0, {%1, %1};" : "=l"(wvv) : "f"(wv));
                asm("fma.rn.f32x2 %0, %1, %2, %0;" : "+l"(t01[i]) : "l"(wvv), "l"(h01));
                asm("fma.rn.f32x2 %0, %1, %2, %0;" : "+l"(t23[i]) : "l"(wvv), "l"(h23));
            }
        }

        // leaky + consume with x_j (leaky(v) = max(v, 0.01v) since slope<1)
        float m0 = 0.f, m1 = 0.f, m2 = 0.f, m3 = 0.f;
        #pragma unroll
        for (int i = 0; i < 32; i++) {
            float v0, v1, v2, v3;
            asm("mov.b64 {%0, %1}, %2;" : "=f"(v0), "=f"(v1) : "l"(t01[i]));
            asm("mov.b64 {%0, %1}, %2;" : "=f"(v2), "=f"(v3) : "l"(t23[i]));
            float4 xq = *(const float4*)(xjT + i * 4);   // broadcast LDS.128
            v0 = fmaxf(v0, SLOPE * v0);
            v1 = fmaxf(v1, SLOPE * v1);
            v2 = fmaxf(v2, SLOPE * v2);
            v3 = fmaxf(v3, SLOPE * v3);
            m0 = fmaf(xq.x, v0, m0);
            m1 = fmaf(xq.y, v1, m1);
            m2 = fmaf(xq.z, v2, m2);
            m3 = fmaf(xq.w, v3, m3);
        }

        atomicAdd(&out[dsts[0] * OD + lane], m0);
        atomicAdd(&out[dsts[1] * OD + lane], m1);
        atomicAdd(&out[dsts[2] * OD + lane], m2);
        atomicAdd(&out[dsts[3] * OD + lane], m3);
        __syncwarp();   // staging reuse next iteration
    }
}

// ---------------------------------------------------------------------------
extern "C" void kernel_launch(void* const* d_in, const int* in_sizes, int n_in,
                              void* d_out, int out_size)
{
    const float* x    = (const float*)d_in[0];
    const int*   ei   = (const int*)d_in[1];     // int32 view; dtype detected on device
    const float* ea   = (const float*)d_in[2];
    // d_in[3] = batch (unused)
    const float* W1   = (const float*)d_in[4];
    const float* b1   = (const float*)d_in[5];
    const float* g1   = (const float*)d_in[6];
    const float* be1  = (const float*)d_in[7];
    const float* m1   = (const float*)d_in[8];
    const float* v1   = (const float*)d_in[9];
    const float* W2   = (const float*)d_in[10];
    const float* b2   = (const float*)d_in[11];
    const float* g2   = (const float*)d_in[12];
    const float* be2  = (const float*)d_in[13];
    const float* m2   = (const float*)d_in[14];
    const float* v2   = (const float*)d_in[15];
    const float* root = (const float*)d_in[16];
    const float* bias = (const float*)d_in[17];
    float* out = (float*)d_out;

    const int smem_bytes = (HD * NCOL + NCOL + ED * HD + HD + NWARP * 320) * (int)sizeof(float);
    cudaFuncSetAttribute(edge_kernel, cudaFuncAttributeMaxDynamicSharedMemorySize, smem_bytes);

    fold_kernel<<<(HD * NCOL + 255) / 256, 256>>>(W1, b1, g1, be1, m1, v1,
                                                  W2, b2, g2, be2, m2, v2, ei);
    init_kernel<<<(NN + 7) / 8, BLOCK>>>(x, root, bias, out);
    edge_kernel<<<EGRID, BLOCK, smem_bytes>>>(x, ei, ea, out);
}

// round 5
// speedup vs baseline: 3.0506x; 3.0506x over previous
#include <cuda_runtime.h>
#include <cuda_bf16.h>
#include <cstdint>

#define NN 50000
#define NE 200000
#define EPSV 1e-5f
#define SLOPE 0.01f
#define NTILES 1563          // ceil(NE/128)
#define EGRID 148

#define BSTRIDE 144          // bytes per smem row for A and B tiles (16B-mult, conflict-free ldmatrix)

// ---- dynamic smem byte offsets ----
#define OFF_BS   0           // B_aug [1024 n][64 k bf16 + pad]   147456 B
#define OFF_AS   147456      // A_aug [128 e][64 k bf16 + pad]     18432 B
#define OFF_XJ   165888      // xjT [32 i][128 e] float            16384 B
#define OFF_MSG  182272      // msg [2 Nw][128 e][33] float        33792 B
#define OFF_B2S  216064      // 1024 float
#define OFF_W1S  220160      // 512 float
#define OFF_B1S  222208      // 32 float
#define OFF_DST  222336      // 128 int
#define SMEM_BYTES 222848

// folded / preprocessed weights
__device__ __nv_bfloat16 g_Baug[1024 * 64];  // [n][k]: k0..31 = hi(W2f[k][n]), k32..63 = lo
__device__ float g_b2f[1024];
__device__ float g_W1f[512];                 // [d][k]
__device__ float g_b1f[32];
__device__ int   g_is64;

// ---------------- helpers ----------------
static __device__ __forceinline__ uint32_t smem_u32(const void* p) {
    uint32_t a;
    asm("{ .reg .u64 t; cvta.to.shared.u64 t, %1; cvt.u32.u64 %0, t; }" : "=r"(a) : "l"(p));
    return a;
}
static __device__ __forceinline__ void ldsm4(uint32_t r[4], uint32_t addr) {
    asm volatile("ldmatrix.sync.aligned.m8n8.x4.shared.b16 {%0,%1,%2,%3}, [%4];"
        : "=r"(r[0]), "=r"(r[1]), "=r"(r[2]), "=r"(r[3]) : "r"(addr));
}
static __device__ __forceinline__ void ldsm2(uint32_t r[2], uint32_t addr) {
    asm volatile("ldmatrix.sync.aligned.m8n8.x2.shared.b16 {%0,%1}, [%2];"
        : "=r"(r[0]), "=r"(r[1]) : "r"(addr));
}
static __device__ __forceinline__ void mma_bf16(float c[4], const uint32_t a[4], const uint32_t b[2]) {
    asm volatile("mma.sync.aligned.m16n8k16.row.col.f32.bf16.bf16.f32 "
        "{%0,%1,%2,%3}, {%4,%5,%6,%7}, {%8,%9}, {%0,%1,%2,%3};"
        : "+f"(c[0]), "+f"(c[1]), "+f"(c[2]), "+f"(c[3])
        : "r"(a[0]), "r"(a[1]), "r"(a[2]), "r"(a[3]), "r"(b[0]), "r"(b[1]));
}

// ---------------------------------------------------------------------------
// fold: BN into weights; W2f -> bf16 hi/lo split stored n-major [n][64].
// ---------------------------------------------------------------------------
__global__ void fold_kernel(const float* __restrict__ W1, const float* __restrict__ b1,
                            const float* __restrict__ g1, const float* __restrict__ be1,
                            const float* __restrict__ m1, const float* __restrict__ v1,
                            const float* __restrict__ W2, const float* __restrict__ b2,
                            const float* __restrict__ g2, const float* __restrict__ be2,
                            const float* __restrict__ m2, const float* __restrict__ v2,
                            const int* __restrict__ ei32)
{
    int idx = blockIdx.x * blockDim.x + threadIdx.x;   // 0..32767
    if (idx >= 32768) return;
    int n = idx & 1023;
    int k = idx >> 10;                                 // 0..31
    float s = g2[n] * rsqrtf(v2[n] + EPSV);
    float w = W2[k * 1024 + n] * s;
    __nv_bfloat16 hi = __float2bfloat16(w);
    __nv_bfloat16 lo = __float2bfloat16(w - __bfloat162float(hi));
    g_Baug[n * 64 + k]      = hi;
    g_Baug[n * 64 + 32 + k] = lo;
    if (k == 0) {
        g_b2f[n] = (b2[n] - m2[n]) * s + be2[n];
        if (n < 32) {
            float s1 = g1[n] * rsqrtf(v1[n] + EPSV);
            g_b1f[n] = (b1[n] - m1[n]) * s1 + be1[n];
            #pragma unroll
            for (int d = 0; d < 16; d++)
                g_W1f[d * 32 + n] = W1[d * 32 + n] * s1;
        }
        if (n == 0) {
            int all0 = 1;
            for (int i = 0; i < 64; i++)
                if (ei32[2 * i + 1] != 0) { all0 = 0; break; }
            g_is64 = all0;
        }
    }
}

// ---------------------------------------------------------------------------
// out[n,:] = bias + x[n,:] @ root
// ---------------------------------------------------------------------------
__global__ void init_kernel(const float* __restrict__ x,
                            const float* __restrict__ root,
                            const float* __restrict__ bias,
                            float* __restrict__ out)
{
    __shared__ float root_s[1024];
    __shared__ float bias_s[32];
    int t = threadIdx.x;
    for (int i = t; i < 1024; i += blockDim.x) root_s[i] = root[i];
    if (t < 32) bias_s[t] = bias[t];
    __syncthreads();
    int lane = t & 31, w = t >> 5;
    int n = blockIdx.x * (blockDim.x >> 5) + w;
    if (n >= NN) return;
    float xv = x[n * 32 + lane];
    float acc = bias_s[lane];
    #pragma unroll
    for (int i = 0; i < 32; i++)
        acc = fmaf(__shfl_sync(0xffffffffu, xv, i), root_s[i * 32 + lane], acc);
    out[n * 32 + lane] = acc;
}

// ---------------------------------------------------------------------------
// Persistent fused edge kernel: mma.sync bf16 split GEMM + fused epilogue.
// ---------------------------------------------------------------------------
extern __shared__ char smem[];

__global__ void __launch_bounds__(256, 1)
edge_kernel(const float* __restrict__ x,
            const int*   __restrict__ ei32,
            const float* __restrict__ edge_attr,
            float* __restrict__ out)
{
    const int tid = threadIdx.x;
    const int lane = tid & 31, wid = tid >> 5;
    const int Mw = wid & 3, Nw = wid >> 2;
    uint32_t su = smem_u32(smem);

    // ---- persistent copies: B_aug, b2f, W1f, b1f ----
    {
        const int4* bs = (const int4*)g_Baug;
        for (int i = tid; i < 8192; i += 256) {
            int n = i >> 3, seg = i & 7;
            *(int4*)(smem + OFF_BS + n * BSTRIDE + seg * 16) = bs[i];
        }
        float* b2w = (float*)(smem + OFF_B2S);
        for (int i = tid; i < 1024; i += 256) b2w[i] = g_b2f[i];
        float* w1w = (float*)(smem + OFF_W1S);
        for (int i = tid; i < 512; i += 256) w1w[i] = g_W1f[i];
        if (tid < 32) ((float*)(smem + OFF_B1S))[tid] = g_b1f[tid];
    }
    const int is64 = g_is64;
    __syncthreads();

    // ldmatrix base addresses
    uint32_t a_base0 = su + OFF_AS + (uint32_t)(Mw * 32 + (lane & 15)) * BSTRIDE + ((lane >> 4) * 8) * 2;
    uint32_t a_base1 = a_base0 + 16 * BSTRIDE;
    uint32_t b_base  = su + OFF_BS + (uint32_t)(Nw * 512 + (lane & 7)) * BSTRIDE + (((lane >> 3) & 1) * 8) * 2;

    const float* b2s = (const float*)(smem + OFF_B2S);
    const float* xj  = (const float*)(smem + OFF_XJ);
    float* ms        = (float*)(smem + OFF_MSG) + Nw * (128 * 33);
    const float* ms0 = (const float*)(smem + OFF_MSG);
    const float* ms1 = ms0 + 128 * 33;
    int* dst_s       = (int*)(smem + OFF_DST);

    for (int tile = blockIdx.x; tile < NTILES; tile += gridDim.x) {
        // ============ phase 1: gather x_j, layer 1, A-tile build ============
        {
            int e = tid >> 1, hf = tid & 1;         // thread pair per edge
            int eid = tile * 128 + e;
            int valid = eid < NE;
            int eidc = valid ? eid : NE - 1;
            int src, dd;
            if (is64) { src = ei32[2 * eidc]; dd = ei32[2 * (NE + eidc)]; }
            else      { src = ei32[eidc];     dd = ei32[NE + eidc]; }
            if (hf == 0) dst_s[e] = valid ? dd : -1;

            // gather x[src] -> xjT[i][e], each half does 16 i's
            float* xjw = (float*)(smem + OFF_XJ);
            const float4* xr = (const float4*)(x + (size_t)src * 32) + hf * 4;
            #pragma unroll
            for (int q = 0; q < 4; q++) {
                float4 v = xr[q];
                int i0 = hf * 16 + q * 4;
                xjw[(i0 + 0) * 128 + e] = v.x;
                xjw[(i0 + 1) * 128 + e] = v.y;
                xjw[(i0 + 2) * 128 + e] = v.z;
                xjw[(i0 + 3) * 128 + e] = v.w;
            }

            // layer 1: h = leaky(ea @ W1f + b1f) (both halves compute full h)
            float hval[32];
            {
                const float* W1s = (const float*)(smem + OFF_W1S);
                const float* b1s = (const float*)(smem + OFF_B1S);
                #pragma unroll
                for (int k = 0; k < 32; k++) hval[k] = b1s[k];
                const float4* er = (const float4*)(edge_attr + (size_t)eidc * 16);
                #pragma unroll
                for (int qq = 0; qq < 4; qq++) {
                    float4 q = er[qq];
                    float ev[4] = {q.x, q.y, q.z, q.w};
                    #pragma unroll
                    for (int dj = 0; dj < 4; dj++) {
                        int d = qq * 4 + dj;
                        #pragma unroll
                        for (int k = 0; k < 32; k++)
                            hval[k] = fmaf(ev[dj], W1s[d * 32 + k], hval[k]);
                    }
                }
                #pragma unroll
                for (int k = 0; k < 32; k++) hval[k] = fmaxf(hval[k], SLOPE * hval[k]);
            }

            // A row: half 0 writes hi(h) to k0..31, half 1 writes lo(h) to k32..63
            union { __nv_bfloat162 h2[16]; uint4 u4[4]; } pk;
            if (hf == 0) {
                #pragma unroll
                for (int j = 0; j < 16; j++)
                    pk.h2[j] = __nv_bfloat162(__float2bfloat16(hval[2 * j]),
                                              __float2bfloat16(hval[2 * j + 1]));
            } else {
                #pragma unroll
                for (int j = 0; j < 16; j++) {
                    float v0 = hval[2 * j], v1 = hval[2 * j + 1];
                    __nv_bfloat16 h0 = __float2bfloat16(v0), h1 = __float2bfloat16(v1);
                    pk.h2[j] = __nv_bfloat162(__float2bfloat16(v0 - __bfloat162float(h0)),
                                              __float2bfloat16(v1 - __bfloat162float(h1)));
                }
            }
            char* arow = smem + OFF_AS + e * BSTRIDE + hf * 64;
            #pragma unroll
            for (int q = 0; q < 4; q++) *(uint4*)(arow + q * 16) = pk.u4[q];
        }
        __syncthreads();

        // ============ phase 2: MMA + fused epilogue ============
        // a-frags: f0,f1 = h_hi (k0-31), f2,f3 = h_lo (k32-63); 2 row-chunks
        uint32_t af0[4][4], af1[4][4];
        #pragma unroll
        for (int f = 0; f < 4; f++) {
            ldsm4(af0[f], a_base0 + f * 32);
            ldsm4(af1[f], a_base1 + f * 32);
        }

        float msg[2][2][4][2];
        #pragma unroll
        for (int a1 = 0; a1 < 2; a1++)
            #pragma unroll
            for (int a2 = 0; a2 < 2; a2++)
                #pragma unroll
                for (int a3 = 0; a3 < 4; a3++)
                    { msg[a1][a2][a3][0] = 0.f; msg[a1][a2][a3][1] = 0.f; }

        const int r0 = Mw * 32 + (lane >> 2);

        for (int nbo = 0; nbo < 64; nbo += 4) {
            #pragma unroll
            for (int nbq = 0; nbq < 4; nbq++) {
                int nb = nbo + nbq;
                int n0 = Nw * 512 + nb * 8;
                uint32_t ba = b_base + (uint32_t)(nb * 8) * BSTRIDE;
                uint32_t g0[2], g1[2], g2[2], g3[2];
                ldsm2(g0, ba);         // W_hi k0-15
                ldsm2(g1, ba + 32);    // W_hi k16-31
                ldsm2(g2, ba + 64);    // W_lo k0-15
                ldsm2(g3, ba + 96);    // W_lo k16-31
                float2 b2v = *(const float2*)(b2s + n0 + (lane & 3) * 2);
                int ii = n0 >> 5;

                float c0[4] = {0.f, 0.f, 0.f, 0.f};
                float c1[4] = {0.f, 0.f, 0.f, 0.f};
                // hi*Whi + hi*Wlo + lo*Whi  (chunks interleaved for ILP)
                mma_bf16(c0, af0[0], g0);  mma_bf16(c1, af1[0], g0);
                mma_bf16(c0, af0[1], g1);  mma_bf16(c1, af1[1], g1);
                mma_bf16(c0, af0[0], g2);  mma_bf16(c1, af1[0], g2);
                mma_bf16(c0, af0[1], g3);  mma_bf16(c1, af1[1], g3);
                mma_bf16(c0, af0[2], g0);  mma_bf16(c1, af1[2], g0);
                mma_bf16(c0, af0[3], g1);  mma_bf16(c1, af1[3], g1);

                float xv00 = xj[ii * 128 + r0];
                float xv01 = xj[ii * 128 + r0 + 8];
                float xv10 = xj[ii * 128 + r0 + 16];
                float xv11 = xj[ii * 128 + r0 + 24];
                float v;
                v = c0[0] + b2v.x; v = fmaxf(v, SLOPE * v); msg[0][0][nbq][0] = fmaf(xv00, v, msg[0][0][nbq][0]);
                v = c0[1] + b2v.y; v = fmaxf(v, SLOPE * v); msg[0][0][nbq][1] = fmaf(xv00, v, msg[0][0][nbq][1]);
                v = c0[2] + b2v.x; v = fmaxf(v, SLOPE * v); msg[0][1][nbq][0] = fmaf(xv01, v, msg[0][1][nbq][0]);
                v = c0[3] + b2v.y; v = fmaxf(v, SLOPE * v); msg[0][1][nbq][1] = fmaf(xv01, v, msg[0][1][nbq][1]);
                v = c1[0] + b2v.x; v = fmaxf(v, SLOPE * v); msg[1][0][nbq][0] = fmaf(xv10, v, msg[1][0][nbq][0]);
                v = c1[1] + b2v.y; v = fmaxf(v, SLOPE * v); msg[1][0][nbq][1] = fmaf(xv10, v, msg[1][0][nbq][1]);
                v = c1[2] + b2v.x; v = fmaxf(v, SLOPE * v); msg[1][1][nbq][0] = fmaf(xv11, v, msg[1][1][nbq][0]);
                v = c1[3] + b2v.y; v = fmaxf(v, SLOPE * v); msg[1][1][nbq][1] = fmaf(xv11, v, msg[1][1][nbq][1]);
            }
        }

        // ============ phase 3: msg -> smem, sum halves, coalesced atomics ============
        #pragma unroll
        for (int ch = 0; ch < 2; ch++)
            #pragma unroll
            for (int rh = 0; rh < 2; rh++)
                #pragma unroll
                for (int j = 0; j < 4; j++)
                    #pragma unroll
                    for (int d = 0; d < 2; d++) {
                        int row = Mw * 32 + ch * 16 + rh * 8 + (lane >> 2);
                        int o = (lane & 3) * 2 + 8 * j + d;
                        ms[row * 33 + o] = msg[ch][rh][j][d];
                    }
        __syncthreads();

        #pragma unroll 1
        for (int ee = 0; ee < 16; ee++) {
            int e2 = wid * 16 + ee;
            int dd = dst_s[e2];
            if (dd >= 0)
                atomicAdd(out + (size_t)dd * 32 + lane,
                          ms0[e2 * 33 + lane] + ms1[e2 * 33 + lane]);
        }
        __syncthreads();   // protect dst_s/xj/A before next tile's writes
    }
}

// ---------------------------------------------------------------------------
extern "C" void kernel_launch(void* const* d_in, const int* in_sizes, int n_in,
                              void* d_out, int out_size)
{
    const float* x    = (const float*)d_in[0];
    const int*   ei   = (const int*)d_in[1];
    const float* ea   = (const float*)d_in[2];
    const float* W1   = (const float*)d_in[4];
    const float* b1   = (const float*)d_in[5];
    const float* g1   = (const float*)d_in[6];
    const float* be1  = (const float*)d_in[7];
    const float* m1   = (const float*)d_in[8];
    const float* v1   = (const float*)d_in[9];
    const float* W2   = (const float*)d_in[10];
    const float* b2   = (const float*)d_in[11];
    const float* g2   = (const float*)d_in[12];
    const float* be2  = (const float*)d_in[13];
    const float* m2   = (const float*)d_in[14];
    const float* v2   = (const float*)d_in[15];
    const float* root = (const float*)d_in[16];
    const float* bias = (const float*)d_in[17];
    float* out = (float*)d_out;

    cudaFuncSetAttribute(edge_kernel, cudaFuncAttributeMaxDynamicSharedMemorySize, SMEM_BYTES);

    fold_kernel<<<128, 256>>>(W1, b1, g1, be1, m1, v1, W2, b2, g2, be2, m2, v2, ei);
    init_kernel<<<(NN + 7) / 8, 256>>>(x, root, bias, out);
    edge_kernel<<<EGRID, 256, SMEM_BYTES>>>(x, ei, ea, out);
}